// round 6
// baseline (speedup 1.0000x reference)
#include <cuda_runtime.h>
#include <cuda_bf16.h>
#include <math.h>
#include <stdint.h>

#define N_NODES 20000
#define N_EDGES 320000
#define NE_TOT  (N_EDGES + N_NODES)   /* 340000 incl self loops */
#define IN_CH   512
#define HID     128
#define HEADS   4
#define OUT_CH  256
#define L1_F    (HEADS * HID)         /* 512 */

#define A1_OFF  (N_NODES * OUT_CH)            /* 5,120,000 */
#define A2_OFF  (A1_OFF + NE_TOT * HEADS)     /* 6,480,000 */

/* ------------------------- scratch (device globals) ------------------------- */
__device__ float         g_h1[(size_t)N_NODES * L1_F];
__device__ float         g_h2[(size_t)N_NODES * OUT_CH];
__device__ __nv_bfloat16 g_xhi[(size_t)N_NODES * IN_CH];
__device__ __nv_bfloat16 g_xlo[(size_t)N_NODES * IN_CH];
__device__ __nv_bfloat16 g_w1hi[L1_F * IN_CH];      /* transposed [N][K] */
__device__ __nv_bfloat16 g_w1lo[L1_F * IN_CH];
__device__ __nv_bfloat16 g_w2hi[OUT_CH * L1_F];
__device__ __nv_bfloat16 g_w2lo[OUT_CH * L1_F];
__device__ __nv_bfloat16 g_a1hi[(size_t)N_NODES * L1_F];
__device__ __nv_bfloat16 g_a1lo[(size_t)N_NODES * L1_F];
__device__ float g_as1[N_NODES * HEADS];
__device__ float g_ad1[N_NODES * HEADS];
__device__ float g_as2[N_NODES];
__device__ float g_ad2[N_NODES];
__device__ float g_vbuf[(size_t)NE_TOT * HEADS];    /* [head][csr_pos] */
__device__ int   g_counts[N_NODES];
__device__ int   g_cursor[N_NODES];
__device__ int   g_rowptr[N_NODES + 1];
__device__ int   g_esrc[NE_TOT];
__device__ int   g_eorig[NE_TOT];

/* ------------------------- helpers ------------------------- */
__device__ __forceinline__ uint32_t smem_u32(const void* p) {
    uint32_t a;
    asm("{ .reg .u64 t; cvta.to.shared.u64 t, %1; cvt.u32.u64 %0, t; }" : "=r"(a) : "l"(p));
    return a;
}
__device__ __forceinline__ void ldsm_x4(uint32_t& r0, uint32_t& r1, uint32_t& r2,
                                        uint32_t& r3, uint32_t addr) {
    asm volatile("ldmatrix.sync.aligned.m8n8.x4.shared.b16 {%0,%1,%2,%3}, [%4];"
                 : "=r"(r0), "=r"(r1), "=r"(r2), "=r"(r3) : "r"(addr));
}
__device__ __forceinline__ void mma_bf16(float* d, const uint32_t* a, const uint32_t* b) {
    asm volatile("mma.sync.aligned.m16n8k16.row.col.f32.bf16.bf16.f32 "
                 "{%0,%1,%2,%3}, {%4,%5,%6,%7}, {%8,%9}, {%0,%1,%2,%3};"
                 : "+f"(d[0]), "+f"(d[1]), "+f"(d[2]), "+f"(d[3])
                 : "r"(a[0]), "r"(a[1]), "r"(a[2]), "r"(a[3]), "r"(b[0]), "r"(b[1]));
}
__device__ __forceinline__ void cpa16(uint32_t dst, const void* src) {
    asm volatile("cp.async.cg.shared.global [%0], [%1], 16;" :: "r"(dst), "l"(src));
}
#define CP_COMMIT() asm volatile("cp.async.commit_group;" ::: "memory")
#define CP_WAIT0()  asm volatile("cp.async.wait_group 0;" ::: "memory")

/* ------------------------- CSR construction ------------------------- */
__device__ __forceinline__ void edge_nodes(const int* __restrict__ ei, int e,
                                           int& src, int& dst) {
    if (e < N_EDGES) { src = ei[e]; dst = ei[N_EDGES + e]; }
    else             { src = dst = e - N_EDGES; }
}

__global__ void count_deg(const int* __restrict__ ei) {
    int e = blockIdx.x * blockDim.x + threadIdx.x;
    if (e >= NE_TOT) return;
    int src, dst;
    edge_nodes(ei, e, src, dst);
    atomicAdd(&g_counts[dst], 1);
}

__global__ void scan_rowptr() {
    __shared__ int wsum[32];
    __shared__ int s_carry;
    int tid = threadIdx.x, lane = tid & 31, wid = tid >> 5;
    if (tid == 0) { g_rowptr[0] = 0; s_carry = 0; }
    __syncthreads();
    for (int base = 0; base < N_NODES; base += 1024) {
        int i = base + tid;
        int v = (i < N_NODES) ? g_counts[i] : 0;
        int x = v;
#pragma unroll
        for (int o = 1; o < 32; o <<= 1) {
            int t = __shfl_up_sync(0xFFFFFFFFu, x, o);
            if (lane >= o) x += t;
        }
        if (lane == 31) wsum[wid] = x;
        __syncthreads();
        if (wid == 0) {
            int s = wsum[lane];
#pragma unroll
            for (int o = 1; o < 32; o <<= 1) {
                int t = __shfl_up_sync(0xFFFFFFFFu, s, o);
                if (lane >= o) s += t;
            }
            wsum[lane] = s;
        }
        __syncthreads();
        int inc = x + (wid > 0 ? wsum[wid - 1] : 0) + s_carry;
        if (i < N_NODES) g_rowptr[i + 1] = inc;
        __syncthreads();
        if (tid == 1023) s_carry = inc;
        __syncthreads();
    }
}

__global__ void scatter_edges(const int* __restrict__ ei) {
    int e = blockIdx.x * blockDim.x + threadIdx.x;
    if (e >= NE_TOT) return;
    int src, dst;
    edge_nodes(ei, e, src, dst);
    int pos = g_rowptr[dst] + atomicAdd(&g_cursor[dst], 1);
    g_esrc[pos]  = src;
    g_eorig[pos] = e;
}

/* ------------------------- fp32 -> bf16 hi/lo splits ------------------------- */
/* also zeroes CSR counters + as/ad accumulators */
__global__ void split_fp32_zero(const float* __restrict__ in,
                                __nv_bfloat16* __restrict__ hi,
                                __nv_bfloat16* __restrict__ lo, int n) {
    int i = blockIdx.x * blockDim.x + threadIdx.x;
    if (i < N_NODES) { g_counts[i] = 0; g_cursor[i] = 0; g_as2[i] = 0.f; g_ad2[i] = 0.f; }
    if (i < N_NODES * HEADS) { g_as1[i] = 0.f; g_ad1[i] = 0.f; }
    if (i >= n) return;
    float v = in[i];
    __nv_bfloat16 h = __float2bfloat16(v);
    hi[i] = h;
    lo[i] = __float2bfloat16(v - __bfloat162float(h));
}

/* W [K][N] -> out [N][K] bf16 hi/lo */
__global__ void split_w_t(const float* __restrict__ W,
                          __nv_bfloat16* __restrict__ thi,
                          __nv_bfloat16* __restrict__ tlo, int K, int N) {
    int i = blockIdx.x * blockDim.x + threadIdx.x;
    if (i >= K * N) return;
    int k = i / N, n = i % N;
    float v = W[i];
    __nv_bfloat16 h = __float2bfloat16(v);
    thi[n * K + k] = h;
    tlo[n * K + k] = __float2bfloat16(v - __bfloat162float(h));
}

/* ------------------------- HMMA bf16-split GEMM (cp.async) ------------------
   C[M,N] fp32 ≈ Ahi*Bhi^T + Alo*Bhi^T + Ahi*Blo^T; A [M,K], B [N,K] bf16.
   K=512. CTA tile 128x128, 8 warps (4m x 2n), warp tile 32x64.
   Epilogue ALSO computes attention coefficients:
     as[row*H + head] += <h[row, n0:n0+128], asrc[n0:n0+128]>   (flattened heads)
   HC = per-head feature dim; head = global_n / HC (constant per warp). */
#define KSTAGES (512 / 16)    /* 32 */
#define SROW    24

__global__ __launch_bounds__(256)
void gemm_hmma(const __nv_bfloat16* __restrict__ Ahi, const __nv_bfloat16* __restrict__ Alo,
               const __nv_bfloat16* __restrict__ Bhi, const __nv_bfloat16* __restrict__ Blo,
               float* __restrict__ C, int M, int N,
               const float* __restrict__ asrc, const float* __restrict__ adst,
               float* __restrict__ as_out, float* __restrict__ ad_out,
               int HC, int H) {
    __shared__ __align__(16) __nv_bfloat16 sA[2][2][128][SROW]; /* [buf][hi/lo] */
    __shared__ __align__(16) __nv_bfloat16 sB[2][2][128][SROW];

    int tid = threadIdx.x, wid = tid >> 5, lane = tid & 31;
    int m0 = blockIdx.y * 128, n0 = blockIdx.x * 128;
    int wm = (wid >> 1) * 32;
    int wn = (wid & 1) * 64;

    /* gmem load coords: thread loads one 16B chunk per plane per stage */
    int prow = tid >> 1, pseg = tid & 1;
    int agr = m0 + prow; if (agr >= M) agr = M - 1;
    const __nv_bfloat16* pAhi = Ahi + (size_t)agr * 512 + pseg * 8;
    const __nv_bfloat16* pAlo = Alo + (size_t)agr * 512 + pseg * 8;
    const __nv_bfloat16* pBhi = Bhi + (size_t)(n0 + prow) * 512 + pseg * 8;
    const __nv_bfloat16* pBlo = Blo + (size_t)(n0 + prow) * 512 + pseg * 8;
    uint32_t dA0[2], dA1[2], dB0[2], dB1[2];
#pragma unroll
    for (int b = 0; b < 2; b++) {
        dA0[b] = smem_u32(&sA[b][0][prow][pseg * 8]);
        dA1[b] = smem_u32(&sA[b][1][prow][pseg * 8]);
        dB0[b] = smem_u32(&sB[b][0][prow][pseg * 8]);
        dB1[b] = smem_u32(&sB[b][1][prow][pseg * 8]);
    }

    /* ldmatrix lane addresses */
    int a_row = (lane & 15), a_k = (lane >> 4) * 8;
    int b_nrow = ((lane >> 4) << 3) + (lane & 7), b_k = ((lane >> 3) & 1) * 8;
    uint32_t a_base0 = smem_u32(&sA[0][0][wm + a_row][a_k]);
    uint32_t a_base1 = smem_u32(&sA[0][1][wm + a_row][a_k]);
    uint32_t b_base0 = smem_u32(&sB[0][0][wn + b_nrow][b_k]);
    uint32_t b_base1 = smem_u32(&sB[0][1][wn + b_nrow][b_k]);
    const uint32_t BUFSTRIDE = 2 * 128 * SROW * 2;

    float acc[2][8][4];
#pragma unroll
    for (int i = 0; i < 2; i++)
#pragma unroll
        for (int j = 0; j < 8; j++)
#pragma unroll
            for (int q = 0; q < 4; q++) acc[i][j][q] = 0.f;

    /* preload stage 0 */
    cpa16(dA0[0], pAhi);
    cpa16(dA1[0], pAlo);
    cpa16(dB0[0], pBhi);
    cpa16(dB1[0], pBlo);
    CP_COMMIT();
    CP_WAIT0();
    __syncthreads();

    for (int t = 0; t < KSTAGES; t++) {
        int buf = t & 1;
        if (t + 1 < KSTAGES) {
            int nb = (t + 1) & 1, ko = (t + 1) * 16;
            cpa16(dA0[nb], pAhi + ko);
            cpa16(dA1[nb], pAlo + ko);
            cpa16(dB0[nb], pBhi + ko);
            cpa16(dB1[nb], pBlo + ko);
            CP_COMMIT();
        }

        uint32_t abase = buf * BUFSTRIDE;
        uint32_t ahi[2][4], alo[2][4];
#pragma unroll
        for (int ma = 0; ma < 2; ma++) {
            ldsm_x4(ahi[ma][0], ahi[ma][1], ahi[ma][2], ahi[ma][3],
                    a_base0 + abase + ma * 16 * SROW * 2);
            ldsm_x4(alo[ma][0], alo[ma][1], alo[ma][2], alo[ma][3],
                    a_base1 + abase + ma * 16 * SROW * 2);
        }
        uint32_t bhi[4][4], blo[4][4];
#pragma unroll
        for (int g = 0; g < 4; g++) {
            ldsm_x4(bhi[g][0], bhi[g][1], bhi[g][2], bhi[g][3],
                    b_base0 + abase + g * 16 * SROW * 2);
            ldsm_x4(blo[g][0], blo[g][1], blo[g][2], blo[g][3],
                    b_base1 + abase + g * 16 * SROW * 2);
        }

#pragma unroll
        for (int ma = 0; ma < 2; ma++)
#pragma unroll
            for (int g = 0; g < 4; g++)
#pragma unroll
                for (int h = 0; h < 2; h++) {
                    float* d = acc[ma][g * 2 + h];
                    mma_bf16(d, ahi[ma], &bhi[g][h * 2]);
                    mma_bf16(d, alo[ma], &bhi[g][h * 2]);
                    mma_bf16(d, ahi[ma], &blo[g][h * 2]);
                }

        CP_WAIT0();
        __syncthreads();
    }

    /* epilogue: write fp32 C + attention coefficient partial dots */
    int lg = lane >> 2, lt = lane & 3;
    int head = (n0 + wn) / HC;
    float ssrc[2][2], sdst[2][2];
#pragma unroll
    for (int i = 0; i < 2; i++)
#pragma unroll
        for (int j = 0; j < 2; j++) { ssrc[i][j] = 0.f; sdst[i][j] = 0.f; }

#pragma unroll
    for (int ma = 0; ma < 2; ma++) {
        int mrow0 = m0 + wm + ma * 16 + lg;
#pragma unroll
        for (int nb = 0; nb < 8; nb++) {
            int n = n0 + wn + nb * 8 + lt * 2;
            float* d = acc[ma][nb];
            float w0s = asrc[n], w1s = asrc[n + 1];
            float w0d = adst[n], w1d = adst[n + 1];
            ssrc[ma][0] += d[0] * w0s + d[1] * w1s;
            sdst[ma][0] += d[0] * w0d + d[1] * w1d;
            ssrc[ma][1] += d[2] * w0s + d[3] * w1s;
            sdst[ma][1] += d[2] * w0d + d[3] * w1d;
            if (mrow0 < M)
                *(float2*)(C + (size_t)mrow0 * N + n) = make_float2(d[0], d[1]);
            if (mrow0 + 8 < M)
                *(float2*)(C + (size_t)(mrow0 + 8) * N + n) = make_float2(d[2], d[3]);
        }
    }
    /* reduce over the 4 lanes (lt) sharing each row, then atomically accumulate */
#pragma unroll
    for (int ma = 0; ma < 2; ma++)
#pragma unroll
        for (int rh = 0; rh < 2; rh++) {
            float vs = ssrc[ma][rh], vd = sdst[ma][rh];
            vs += __shfl_xor_sync(0xFFFFFFFFu, vs, 1);
            vs += __shfl_xor_sync(0xFFFFFFFFu, vs, 2);
            vd += __shfl_xor_sync(0xFFFFFFFFu, vd, 1);
            vd += __shfl_xor_sync(0xFFFFFFFFu, vd, 2);
            int row = m0 + wm + ma * 16 + rh * 8 + lg;
            if (lt == 0 && row < M) {
                atomicAdd(&as_out[row * H + head], vs);
                atomicAdd(&ad_out[row * H + head], vd);
            }
        }
}

/* ------------------------- fused softmax + aggregate ------------------------- */
template <int H, int C, bool ELU, bool SPLIT>
__global__ __launch_bounds__(256)
void fused_agg(const float* __restrict__ as, const float* __restrict__ ad,
               const float* __restrict__ hfeat, const float* __restrict__ bias,
               float* __restrict__ alpha_out, float* __restrict__ aggout,
               __nv_bfloat16* __restrict__ ohi, __nv_bfloat16* __restrict__ olo) {
    int gw = (blockIdx.x * blockDim.x + threadIdx.x) >> 5;
    int lane = threadIdx.x & 31;
    if (gw >= N_NODES * H) return;
    int dst = gw / H, hh = gw % H;

    int beg = g_rowptr[dst], end = g_rowptr[dst + 1];
    float adv = ad[dst * H + hh];
    float* vb = g_vbuf + (size_t)hh * NE_TOT;

    /* pass 1: gather logits once, store contiguously, track max */
    float mx = -1e30f;
    for (int i = beg + lane; i < end; i += 32) {
        float v = as[g_esrc[i] * H + hh] + adv;
        v = v > 0.f ? v : 0.2f * v;
        vb[i] = v;
        mx = fmaxf(mx, v);
    }
#pragma unroll
    for (int o = 16; o; o >>= 1) mx = fmaxf(mx, __shfl_xor_sync(0xFFFFFFFFu, mx, o));

    /* pass 2: denom from contiguous buffer */
    float sm = 0.f;
    for (int i = beg + lane; i < end; i += 32) sm += __expf(vb[i] - mx);
#pragma unroll
    for (int o = 16; o; o >>= 1) sm += __shfl_xor_sync(0xFFFFFFFFu, sm, o);
    float inv = 1.f / sm;

    /* pass 3: alpha + gather-accumulate (software pipelined, depth 2) */
    constexpr int R = C / 128;
    float4 acc[R];
#pragma unroll
    for (int r = 0; r < R; r++) acc[r] = make_float4(0.f, 0.f, 0.f, 0.f);

    int i = beg;
    int s = g_esrc[i];
    int eo = g_eorig[i];
    float vv = vb[i];
    float4 tv[R];
    {
        const float4* hp = (const float4*)(hfeat + (size_t)s * (H * C) + hh * C);
#pragma unroll
        for (int r = 0; r < R; r++) tv[r] = hp[lane + 32 * r];
    }
    for (;;) {
        int inext = i + 1;
        bool more = inext < end;
        int s2 = 0, eo2 = 0;
        float vv2 = 0.f;
        float4 tv2[R];
        if (more) {
            s2 = g_esrc[inext];
            eo2 = g_eorig[inext];
            vv2 = vb[inext];
            const float4* hp2 = (const float4*)(hfeat + (size_t)s2 * (H * C) + hh * C);
#pragma unroll
            for (int r = 0; r < R; r++) tv2[r] = hp2[lane + 32 * r];
        }
        float a = __expf(vv - mx) * inv;
        if (lane == 0) alpha_out[eo * H + hh] = a;
#pragma unroll
        for (int r = 0; r < R; r++) {
            acc[r].x += a * tv[r].x;
            acc[r].y += a * tv[r].y;
            acc[r].z += a * tv[r].z;
            acc[r].w += a * tv[r].w;
        }
        if (!more) break;
        s = s2; eo = eo2; vv = vv2;
#pragma unroll
        for (int r = 0; r < R; r++) tv[r] = tv2[r];
        i = inext;
    }

    /* epilogue: bias (+ELU), fp32 out or bf16 hi/lo split */
#pragma unroll
    for (int r = 0; r < R; r++) {
        int c = (lane + 32 * r) * 4;
        const float* bp = bias + hh * C + c;
        float4 o = acc[r];
        o.x += bp[0]; o.y += bp[1]; o.z += bp[2]; o.w += bp[3];
        if (ELU) {
            o.x = o.x > 0.f ? o.x : expm1f(o.x);
            o.y = o.y > 0.f ? o.y : expm1f(o.y);
            o.z = o.z > 0.f ? o.z : expm1f(o.z);
            o.w = o.w > 0.f ? o.w : expm1f(o.w);
        }
        if (SPLIT) {
            size_t base = (size_t)dst * (H * C) + hh * C + c;
            float vv4[4] = { o.x, o.y, o.z, o.w };
#pragma unroll
            for (int q = 0; q < 4; q++) {
                __nv_bfloat16 h = __float2bfloat16(vv4[q]);
                ohi[base + q] = h;
                olo[base + q] = __float2bfloat16(vv4[q] - __bfloat162float(h));
            }
        } else {
            float* op = aggout + (size_t)dst * (H * C) + hh * C;
            ((float4*)op)[lane + 32 * r] = o;
        }
    }
}

/* ------------------------- launch ------------------------- */
extern "C" void kernel_launch(void* const* d_in, const int* in_sizes, int n_in,
                              void* d_out, int out_size) {
    const float* x      = (const float*)d_in[0];
    const int*   ei     = (const int*)  d_in[1];
    const float* W1     = (const float*)d_in[2];
    const float* a_src1 = (const float*)d_in[3];
    const float* a_dst1 = (const float*)d_in[4];
    const float* b1     = (const float*)d_in[5];
    const float* W2     = (const float*)d_in[6];
    const float* a_src2 = (const float*)d_in[7];
    const float* a_dst2 = (const float*)d_in[8];
    const float* b2     = (const float*)d_in[9];
    float* out = (float*)d_out;

    float *h1, *h2, *as1, *ad1, *as2, *ad2;
    __nv_bfloat16 *xhi, *xlo, *w1hi, *w1lo, *w2hi, *w2lo, *a1hi, *a1lo;
    cudaGetSymbolAddress((void**)&h1,   g_h1);
    cudaGetSymbolAddress((void**)&h2,   g_h2);
    cudaGetSymbolAddress((void**)&as1,  g_as1);
    cudaGetSymbolAddress((void**)&ad1,  g_ad1);
    cudaGetSymbolAddress((void**)&as2,  g_as2);
    cudaGetSymbolAddress((void**)&ad2,  g_ad2);
    cudaGetSymbolAddress((void**)&xhi,  g_xhi);
    cudaGetSymbolAddress((void**)&xlo,  g_xlo);
    cudaGetSymbolAddress((void**)&w1hi, g_w1hi);
    cudaGetSymbolAddress((void**)&w1lo, g_w1lo);
    cudaGetSymbolAddress((void**)&w2hi, g_w2hi);
    cudaGetSymbolAddress((void**)&w2lo, g_w2lo);
    cudaGetSymbolAddress((void**)&a1hi, g_a1hi);
    cudaGetSymbolAddress((void**)&a1lo, g_a1lo);

    /* 0-2: conversions (split_fp32_zero also zeroes CSR counters + as/ad) */
    split_fp32_zero<<<(N_NODES * IN_CH + 255) / 256, 256>>>(x, xhi, xlo, N_NODES * IN_CH);
    split_w_t<<<(IN_CH * L1_F + 255) / 256, 256>>>(W1, w1hi, w1lo, IN_CH, L1_F);
    split_w_t<<<(L1_F * OUT_CH + 255) / 256, 256>>>(W2, w2hi, w2lo, L1_F, OUT_CH);

    /* 3: layer-1 GEMM + attn coefficients (ncu capture slot) */
    gemm_hmma<<<dim3(L1_F / 128, 157), 256>>>(xhi, xlo, w1hi, w1lo, h1, N_NODES, L1_F,
                                              a_src1, a_dst1, as1, ad1, HID, HEADS);

    /* 4-6: CSR build */
    count_deg<<<(NE_TOT + 255) / 256, 256>>>(ei);
    scan_rowptr<<<1, 1024>>>();
    scatter_edges<<<(NE_TOT + 255) / 256, 256>>>(ei);

    /* 7: layer-1 aggregate */
    fused_agg<HEADS, HID, true, true><<<(N_NODES * HEADS + 7) / 8, 256>>>(
        as1, ad1, h1, b1, out + A1_OFF, nullptr, a1hi, a1lo);

    /* 8-9: layer 2 */
    gemm_hmma<<<dim3(OUT_CH / 128, 157), 256>>>(a1hi, a1lo, w2hi, w2lo, h2, N_NODES, OUT_CH,
                                                a_src2, a_dst2, as2, ad2, OUT_CH, 1);
    fused_agg<1, OUT_CH, false, false><<<(N_NODES + 7) / 8, 256>>>(
        as2, ad2, h2, b2, out + A2_OFF, out, nullptr, nullptr);
}